// round 8
// baseline (speedup 1.0000x reference)
#include <cuda_runtime.h>
#include <math.h>

// Problem dims
#define H  8
#define NN 8
#define D  512
#define C  64
#define C2 32
#define I  96
#define SCALE (1.0f/24.0f)   // 1/sqrt(576)

// Output packing (T, M, P, w), float32
#define SZ_T  (NN*C*I*I)
#define OFF_T 0
#define OFF_M (OFF_T + SZ_T)
#define SZ_M  (NN*H*C2)
#define OFF_P (OFF_M + SZ_M)
#define SZ_P  (NN*H*C*I*I)
#define OFF_W (OFF_P + SZ_P)

// ---------------- scratch ----------------
__device__ __align__(16) float g_M  [NN*H*C2];
__device__ __align__(16) float g_Vx [H*C*I];
__device__ __align__(16) float g_Vy [H*C*I];
__device__ __align__(16) float g_Gx [H*C*3*I];
__device__ __align__(16) float g_Gy [H*C*3*I];
__device__ __align__(16) float g_KS2[H*C*9*C2];   // pre-scaled
__device__ __align__(16) float g_KB2[H*C*9];      // pre-scaled, +sb folded

// ============================================================================
// SINGLE setup launch (256 threads/block), all roles independent:
//   [0,256)     : y = X@lw^T + lb -> BN over n -> ReLU -> g_M, out.M
//   [256,768)   : Vx/Vy 1D value fields
//   [768,1280)  : KS2/KB2 tables (input-only: sw, kw, kb, sb)
//   [1280,2304) : folded Gx/Gy tables (input-only: sw, kw, px, py)
// ============================================================================
__global__ void __launch_bounds__(256) k_setup(
    const float* __restrict__ X,  const float* __restrict__ lw,
    const float* __restrict__ lb, const float* __restrict__ gamma,
    const float* __restrict__ beta,
    const float* __restrict__ px, const float* __restrict__ py,
    const float* __restrict__ kw, const float* __restrict__ kb,
    const float* __restrict__ vw,
    const float* __restrict__ sw, const float* __restrict__ sb,
    float* __restrict__ out)
{
    __shared__ float shbuf[6560];
    int b = blockIdx.x;
    int t = threadIdx.x;

    if (b < 256) {
        // ---- y + BN + ReLU -> M ----
        float* red = shbuf;          // 64
        float* sy  = shbuf + 64;     // 8
        int h = b >> 5, c2 = b & 31;
        int wid = t >> 5, lane = t & 31;
        float part[NN];
#pragma unroll
        for (int n = 0; n < NN; n++) part[n] = 0.f;
#pragma unroll
        for (int it = 0; it < 2; it++) {
            int d = t + it*256;
            float w = lw[(h*C2 + c2)*D + d];
#pragma unroll
            for (int n = 0; n < NN; n++) part[n] += w * X[(h*NN + n)*D + d];
        }
#pragma unroll
        for (int off = 16; off; off >>= 1) {
#pragma unroll
            for (int n = 0; n < NN; n++)
                part[n] += __shfl_down_sync(0xffffffffu, part[n], off);
        }
        if (lane == 0) {
#pragma unroll
            for (int n = 0; n < NN; n++) red[wid*NN + n] = part[n];
        }
        __syncthreads();
        if (t < NN) {
            float y = lb[h*C2 + c2];
#pragma unroll
            for (int w = 0; w < 8; w++) y += red[w*NN + t];
            sy[t] = y;
        }
        __syncthreads();
        if (t < NN) {
            float mu = 0.f;
#pragma unroll
            for (int k = 0; k < NN; k++) mu += sy[k];
            mu *= (1.0f/NN);
            float m2 = 0.f;
#pragma unroll
            for (int k = 0; k < NN; k++) { float v = sy[k] - mu; m2 += v*v; }
            float var = m2 * (1.0f/NN);
            float m = (sy[t] - mu) * rsqrtf(var + 1e-5f) * gamma[h*C2 + c2] + beta[h*C2 + c2];
            m = fmaxf(m, 0.f);
            g_M[(t*H + h)*C2 + c2] = m;
            out[OFF_M + (t*H + h)*C2 + c2] = m;
        }
    } else if (b < 768) {
        // ---- Vx/Vy 1D fields ----
        if (t >= I) return;
        int bb = b - 256;            // h*C + cc
        int h = bb >> 6;
        int p = t;
        const float* vwr = vw + bb*C;
        float vx = 0.f, vy = 0.f;
#pragma unroll 8
        for (int c2 = 0; c2 < C2; c2++) {
            vx += vwr[c2]      * px[c2*I + p];
            vy += vwr[c2 + C2] * py[c2*I + p];
        }
        g_Vx[bb*I + p] = vx;
        g_Vy[bb*I + p] = vy;
        (void)h;
    } else if (b < 1280) {
        // ---- KS2 / KB2 ----
        float* swrow = shbuf;                 // 576
        float* s2    = shbuf + 576;           // 64*9
        float* kwsum = shbuf + 1152;          // 64*32
        int idx = b - 768;
        int h = idx >> 6, o = idx & 63;
        for (int q = t; q < 576; q += 256) swrow[q] = sw[o*576 + q];
        for (int q = t; q < 2048; q += 256) {
            int c = q >> 5, c2 = q & 31;
            const float* kr = kw + (h*C + c)*C;
            kwsum[q] = kr[c2] + kr[c2 + C2];
        }
        __syncthreads();
        for (int q = t; q < 576; q += 256) {
            int c = q / 9, v = q % 9, vy = v / 3, vx = v % 3;
            float acc = 0.f;
#pragma unroll
            for (int ky = 0; ky < 3; ky++) {
                if (vy == 0 && ky == 0) continue;
                if (vy == 2 && ky == 2) continue;
#pragma unroll
                for (int kx = 0; kx < 3; kx++) {
                    if (vx == 0 && kx == 0) continue;
                    if (vx == 2 && kx == 2) continue;
                    acc += swrow[c*9 + ky*3 + kx];
                }
            }
            s2[c*9 + v] = acc;
        }
        __syncthreads();
        for (int q = t; q < 288; q += 256) {
            int v = q >> 5, c2 = q & 31;
            float acc = 0.f;
#pragma unroll 8
            for (int c = 0; c < C; c++)
                acc += s2[c*9 + v] * kwsum[c*32 + c2];
            g_KS2[((h*C + o)*9 + v)*C2 + c2] = acc * SCALE;
        }
        if (t < 9) {
            float acc = 0.f;
            for (int c = 0; c < C; c++)
                acc += kb[h*C + c] * s2[c*9 + t];
            g_KB2[(h*C + o)*9 + t] = (acc + sb[o]) * SCALE;
        }
    } else {
        // ---- folded Gx/Gy ----
        float* swrow = shbuf;                 // 576
        float* cs3   = shbuf + 576;           // [c][k][v] 64*9
        float* kwh   = shbuf + 1152;          // 64*32
        float* W     = shbuf + 3200;          // [v][k][c2] 288
        float* pxs   = shbuf + 3488;          // 32*96
        int idx = b - 1280;
        int tab = idx >> 9;
        int r = idx & 511;
        int h = r >> 6, o = r & 63;
        const float* pp = tab ? py : px;
        for (int q = t; q < 576; q += 256) swrow[q] = sw[o*576 + q];
        for (int q = t; q < 2048; q += 256) {
            int c = q >> 5, c2 = q & 31;
            kwh[q] = kw[(h*C + c)*C + c2 + (tab ? C2 : 0)];
        }
        for (int q = t; q < 3072; q += 256) pxs[q] = pp[q];
        __syncthreads();
        for (int q = t; q < 576; q += 256) {
            int c = q / 9, rr = q % 9, k = rr / 3, v = rr % 3;
            float acc = 0.f;
#pragma unroll
            for (int qq = 0; qq < 3; qq++) {
                if (v == 0 && qq == 0) continue;
                if (v == 2 && qq == 2) continue;
                acc += (tab == 0) ? swrow[c*9 + qq*3 + k]
                                  : swrow[c*9 + k*3 + qq];
            }
            cs3[(c*3 + k)*3 + v] = acc;
        }
        __syncthreads();
        for (int q = t; q < 288; q += 256) {
            int v = q / 96, k = (q / 32) % 3, c2 = q & 31;
            float acc = 0.f;
#pragma unroll 8
            for (int c = 0; c < C; c++)
                acc += cs3[(c*3 + k)*3 + v] * kwh[c*32 + c2];
            W[(v*3 + k)*32 + c2] = acc;
        }
        __syncthreads();
        float* dst = tab ? g_Gy : g_Gx;
        for (int q = t; q < 288; q += 256) {
            int v = q / 96, p = q % 96;
            float val = 0.f;
#pragma unroll
            for (int k = 0; k < 3; k++) {
                int ppos = p + k - 1;
                if (ppos < 0 || ppos >= I) continue;
#pragma unroll 8
                for (int c2 = 0; c2 < C2; c2++)
                    val += W[(v*3 + k)*32 + c2] * pxs[c2*96 + ppos];
            }
            dst[((h*C + o)*3 + v)*I + p] = val * SCALE;
        }
    }
}

// ============================================================================
// k_WTP: all 321 MB of stores; Cs/Av computed inline from KS2/KB2/M/vw.
// grid (12, 64, 8), 192 threads (8 ii rows per block)
// ============================================================================
__global__ void __launch_bounds__(192) k_WTP(const float* __restrict__ px,
                                             const float* __restrict__ py,
                                             const float* __restrict__ vw,
                                             const float* __restrict__ vb,
                                             float* __restrict__ out) {
    __shared__ float sGx[H][I];    // vy = 1 slice
    __shared__ float sVx[H][I];
    __shared__ float sPx[I];
    __shared__ float sMall[H][C2];
    __shared__ float sBase[64], sE0[64], sE2[64], sVb[64], sPb[64];

    int t = threadIdx.x;
    int bx = blockIdx.x, c = blockIdx.y, n = blockIdx.z;

    // ---- cooperative staging ----
    for (int q = t; q < H*C2; q += 192)
        sMall[q >> 5][q & 31] = g_M[n*H*C2 + q];
    {
        int h = t / 24, j4 = t % 24;   // exactly 192 slots
        *(float4*)&sGx[h][j4*4] = *(const float4*)(g_Gx + ((h*C + c)*3 + 1)*I + j4*4);
        *(float4*)&sVx[h][j4*4] = *(const float4*)(g_Vx + (h*C + c)*I + j4*4);
    }
    if (c < C2 && t < 24)
        *(float4*)&sPx[t*4] = *(const float4*)(px + c*I + t*4);
    __syncthreads();

    // ---- per-(h,row) scalars: inline Av and Cs ----
    if (t < 64) {
        int h = t >> 3, il = t & 7;
        int ii = bx*8 + il;
        int vy = (ii == 0) ? 0 : (ii == (I-1) ? 2 : 1);
        // Av inline
        const float* vwr = vw + (h*C + c)*C;
        float av = vb[h*C + c];
#pragma unroll 8
        for (int c2 = 0; c2 < C2; c2++)
            av += (vwr[c2] + vwr[c2 + C2]) * sMall[h][c2];
        // Cs inline: 3 vx values for this vy
        const float* ks = g_KS2 + ((h*C + c)*9 + vy*3)*C2;
        const float* kb2 = g_KB2 + (h*C + c)*9 + vy*3;
        float cs0 = kb2[0], cs1 = kb2[1], cs2 = kb2[2];
#pragma unroll 8
        for (int c2 = 0; c2 < C2; c2++) {
            float m = sMall[h][c2];
            cs0 += m * ks[c2];
            cs1 += m * ks[C2 + c2];
            cs2 += m * ks[2*C2 + c2];
        }
        const float* gy = g_Gy + (h*C + c)*3*I;
        sBase[t] = cs1 + gy[I + ii];
        sE0[t]   = cs0 + gy[ii];
        sE2[t]   = cs2 + gy[2*I + ii];
        sVb[t]   = av + g_Vy[(h*C + c)*I + ii];
        sPb[t]   = (c < C2) ? sMall[h][c]
                            : sMall[h][c - C2] + __ldg(py + (c - C2)*I + ii);
    }
    __syncthreads();

    int j4 = t % 24, il = t / 24;        // il in [0,8)
    int ii = bx*8 + il, jj0 = j4*4;
    int vy = (ii == 0) ? 0 : (ii == (I-1) ? 2 : 1);

    float s[H][4];
    float mx0 = -1e30f, mx1 = -1e30f, mx2 = -1e30f, mx3 = -1e30f;
#pragma unroll
    for (int h = 0; h < H; h++) {
        float4 gx = (vy == 1) ? *(const float4*)&sGx[h][jj0]
                              : *(const float4*)(g_Gx + ((h*C + c)*3 + vy)*I + jj0);
        float base = sBase[h*8 + il];
        float s0 = base + gx.x, s1 = base + gx.y, s2 = base + gx.z, s3 = base + gx.w;
        if (jj0 == 0)     s0 = sE0[h*8 + il] + gx.x;
        if (jj0 == I - 4) s3 = sE2[h*8 + il] + gx.w;
        s[h][0] = s0; s[h][1] = s1; s[h][2] = s2; s[h][3] = s3;
        mx0 = fmaxf(mx0, s0); mx1 = fmaxf(mx1, s1);
        mx2 = fmaxf(mx2, s2); mx3 = fmaxf(mx3, s3);
    }
    float sum0 = 0.f, sum1 = 0.f, sum2 = 0.f, sum3 = 0.f;
#pragma unroll
    for (int h = 0; h < H; h++) {
        s[h][0] = __expf(s[h][0] - mx0); sum0 += s[h][0];
        s[h][1] = __expf(s[h][1] - mx1); sum1 += s[h][1];
        s[h][2] = __expf(s[h][2] - mx2); sum2 += s[h][2];
        s[h][3] = __expf(s[h][3] - mx3); sum3 += s[h][3];
    }
    float i0 = __fdividef(1.f, sum0), i1 = __fdividef(1.f, sum1);
    float i2 = __fdividef(1.f, sum2), i3 = __fdividef(1.f, sum3);

    float4 px4 = make_float4(0.f, 0.f, 0.f, 0.f);
    if (c < C2) px4 = *(const float4*)&sPx[jj0];

    float4 acc = make_float4(0.f, 0.f, 0.f, 0.f);
    int pixbase = ii*I + jj0;
#pragma unroll
    for (int h = 0; h < H; h++) {
        float w0 = s[h][0]*i0, w1 = s[h][1]*i1, w2 = s[h][2]*i2, w3 = s[h][3]*i3;
        size_t idx = (size_t)((n*H + h)*C + c)*I*I + pixbase;
        __stcs((float4*)(out + OFF_W + idx), make_float4(w0, w1, w2, w3));

        float vbv = sVb[h*8 + il];
        const float4 vx4 = *(const float4*)&sVx[h][jj0];
        acc.x += w0*(vbv + vx4.x);
        acc.y += w1*(vbv + vx4.y);
        acc.z += w2*(vbv + vx4.z);
        acc.w += w3*(vbv + vx4.w);

        float pb = sPb[h*8 + il];
        float4 pv = (c < C2) ? make_float4(pb + px4.x, pb + px4.y, pb + px4.z, pb + px4.w)
                             : make_float4(pb, pb, pb, pb);
        __stcs((float4*)(out + OFF_P + idx), pv);
    }
    __stcs((float4*)(out + OFF_T + (size_t)(n*C + c)*I*I + pixbase), acc);
}

// ---------------- launch ----------------
extern "C" void kernel_launch(void* const* d_in, const int* in_sizes, int n_in,
                              void* d_out, int out_size) {
    (void)in_sizes; (void)n_in; (void)out_size;
    const float* X     = (const float*)d_in[0];
    const float* lin_w = (const float*)d_in[1];
    const float* lin_b = (const float*)d_in[2];
    const float* gamma = (const float*)d_in[3];
    const float* beta  = (const float*)d_in[4];
    const float* px    = (const float*)d_in[5];
    const float* py    = (const float*)d_in[6];
    const float* kw    = (const float*)d_in[7];
    const float* kb    = (const float*)d_in[8];
    const float* vw    = (const float*)d_in[9];
    const float* vb    = (const float*)d_in[10];
    const float* sw    = (const float*)d_in[11];
    const float* sb    = (const float*)d_in[12];
    float* out = (float*)d_out;

    k_setup<<<2304, 256>>>(X, lin_w, lin_b, gamma, beta, px, py, kw, kb, vw, sw, sb, out);
    k_WTP<<<dim3(12, C, NN), 192>>>(px, py, vw, vb, out);
}

// round 14
// speedup vs baseline: 1.8053x; 1.8053x over previous
#include <cuda_runtime.h>
#include <math.h>

// Problem dims
#define H  8
#define NN 8
#define D  512
#define C  64
#define C2 32
#define I  96
#define SCALE (1.0f/24.0f)   // 1/sqrt(576)

// Output packing (T, M, P, w), float32
#define SZ_T  (NN*C*I*I)
#define OFF_T 0
#define OFF_M (OFF_T + SZ_T)
#define SZ_M  (NN*H*C2)
#define OFF_P (OFF_M + SZ_M)
#define SZ_P  (NN*H*C*I*I)
#define OFF_W (OFF_P + SZ_P)

// ---------------- scratch ----------------
__device__ __align__(16) float g_M  [NN*H*C2];
__device__ __align__(16) float g_Av [NN*H*C];
__device__ __align__(16) float g_Vx [H*C*I];
__device__ __align__(16) float g_Vy [H*C*I];
__device__ __align__(16) float g_Gx [H*C*3*I];
__device__ __align__(16) float g_Gy [H*C*3*I];
__device__ __align__(16) float g_KS2[H*C*9*C2];   // pre-scaled
__device__ __align__(16) float g_KB2[H*C*9];      // pre-scaled, +sb folded
__device__ __align__(16) float g_Cs [NN*H*C*9];

// ============================================================================
// Launch 1 — SINGLE setup launch (256 threads/block), all roles independent:
//   [0,256)     : y = X@lw^T + lb -> BN over n -> ReLU -> g_M, out.M
//   [256,768)   : Vx/Vy 1D value fields
//   [768,1280)  : KS2/KB2 tables (input-only)
//   [1280,2304) : folded Gx/Gy tables (input-only)
// ============================================================================
__global__ void __launch_bounds__(256) k_setup(
    const float* __restrict__ X,  const float* __restrict__ lw,
    const float* __restrict__ lb, const float* __restrict__ gamma,
    const float* __restrict__ beta,
    const float* __restrict__ px, const float* __restrict__ py,
    const float* __restrict__ kw, const float* __restrict__ kb,
    const float* __restrict__ vw,
    const float* __restrict__ sw, const float* __restrict__ sb,
    float* __restrict__ out)
{
    __shared__ float shbuf[6560];
    int b = blockIdx.x;
    int t = threadIdx.x;

    if (b < 256) {
        // ---- y + BN + ReLU -> M ----
        float* red = shbuf;          // 64
        float* sy  = shbuf + 64;     // 8
        int h = b >> 5, c2 = b & 31;
        int wid = t >> 5, lane = t & 31;
        float part[NN];
#pragma unroll
        for (int n = 0; n < NN; n++) part[n] = 0.f;
#pragma unroll
        for (int it = 0; it < 2; it++) {
            int d = t + it*256;
            float w = lw[(h*C2 + c2)*D + d];
#pragma unroll
            for (int n = 0; n < NN; n++) part[n] += w * X[(h*NN + n)*D + d];
        }
#pragma unroll
        for (int off = 16; off; off >>= 1) {
#pragma unroll
            for (int n = 0; n < NN; n++)
                part[n] += __shfl_down_sync(0xffffffffu, part[n], off);
        }
        if (lane == 0) {
#pragma unroll
            for (int n = 0; n < NN; n++) red[wid*NN + n] = part[n];
        }
        __syncthreads();
        if (t < NN) {
            float y = lb[h*C2 + c2];
#pragma unroll
            for (int w = 0; w < 8; w++) y += red[w*NN + t];
            sy[t] = y;
        }
        __syncthreads();
        if (t < NN) {
            float mu = 0.f;
#pragma unroll
            for (int k = 0; k < NN; k++) mu += sy[k];
            mu *= (1.0f/NN);
            float m2 = 0.f;
#pragma unroll
            for (int k = 0; k < NN; k++) { float v = sy[k] - mu; m2 += v*v; }
            float var = m2 * (1.0f/NN);
            float m = (sy[t] - mu) * rsqrtf(var + 1e-5f) * gamma[h*C2 + c2] + beta[h*C2 + c2];
            m = fmaxf(m, 0.f);
            g_M[(t*H + h)*C2 + c2] = m;
            out[OFF_M + (t*H + h)*C2 + c2] = m;
        }
    } else if (b < 768) {
        // ---- Vx/Vy 1D fields ----
        if (t >= I) return;
        int bb = b - 256;            // h*C + cc
        int p = t;
        const float* vwr = vw + bb*C;
        float vx = 0.f, vy = 0.f;
#pragma unroll 8
        for (int c2 = 0; c2 < C2; c2++) {
            vx += vwr[c2]      * px[c2*I + p];
            vy += vwr[c2 + C2] * py[c2*I + p];
        }
        g_Vx[bb*I + p] = vx;
        g_Vy[bb*I + p] = vy;
    } else if (b < 1280) {
        // ---- KS2 / KB2 ----
        float* swrow = shbuf;                 // 576
        float* s2    = shbuf + 576;           // 64*9
        float* kwsum = shbuf + 1152;          // 64*32
        int idx = b - 768;
        int h = idx >> 6, o = idx & 63;
        for (int q = t; q < 576; q += 256) swrow[q] = sw[o*576 + q];
        for (int q = t; q < 2048; q += 256) {
            int c = q >> 5, c2 = q & 31;
            const float* kr = kw + (h*C + c)*C;
            kwsum[q] = kr[c2] + kr[c2 + C2];
        }
        __syncthreads();
        for (int q = t; q < 576; q += 256) {
            int c = q / 9, v = q % 9, vy = v / 3, vx = v % 3;
            float acc = 0.f;
#pragma unroll
            for (int ky = 0; ky < 3; ky++) {
                if (vy == 0 && ky == 0) continue;
                if (vy == 2 && ky == 2) continue;
#pragma unroll
                for (int kx = 0; kx < 3; kx++) {
                    if (vx == 0 && kx == 0) continue;
                    if (vx == 2 && kx == 2) continue;
                    acc += swrow[c*9 + ky*3 + kx];
                }
            }
            s2[c*9 + v] = acc;
        }
        __syncthreads();
        for (int q = t; q < 288; q += 256) {
            int v = q >> 5, c2 = q & 31;
            float acc = 0.f;
#pragma unroll 8
            for (int c = 0; c < C; c++)
                acc += s2[c*9 + v] * kwsum[c*32 + c2];
            g_KS2[((h*C + o)*9 + v)*C2 + c2] = acc * SCALE;
        }
        if (t < 9) {
            float acc = 0.f;
            for (int c = 0; c < C; c++)
                acc += kb[h*C + c] * s2[c*9 + t];
            g_KB2[(h*C + o)*9 + t] = (acc + sb[o]) * SCALE;
        }
    } else {
        // ---- folded Gx/Gy ----
        float* swrow = shbuf;                 // 576
        float* cs3   = shbuf + 576;           // [c][k][v] 64*9
        float* kwh   = shbuf + 1152;          // 64*32
        float* W     = shbuf + 3200;          // [v][k][c2] 288
        float* pxs   = shbuf + 3488;          // 32*96
        int idx = b - 1280;
        int tab = idx >> 9;
        int r = idx & 511;
        int h = r >> 6, o = r & 63;
        const float* pp = tab ? py : px;
        for (int q = t; q < 576; q += 256) swrow[q] = sw[o*576 + q];
        for (int q = t; q < 2048; q += 256) {
            int c = q >> 5, c2 = q & 31;
            kwh[q] = kw[(h*C + c)*C + c2 + (tab ? C2 : 0)];
        }
        for (int q = t; q < 3072; q += 256) pxs[q] = pp[q];
        __syncthreads();
        for (int q = t; q < 576; q += 256) {
            int c = q / 9, rr = q % 9, k = rr / 3, v = rr % 3;
            float acc = 0.f;
#pragma unroll
            for (int qq = 0; qq < 3; qq++) {
                if (v == 0 && qq == 0) continue;
                if (v == 2 && qq == 2) continue;
                acc += (tab == 0) ? swrow[c*9 + qq*3 + k]
                                  : swrow[c*9 + k*3 + qq];
            }
            cs3[(c*3 + k)*3 + v] = acc;
        }
        __syncthreads();
        for (int q = t; q < 288; q += 256) {
            int v = q / 96, k = (q / 32) % 3, c2 = q & 31;
            float acc = 0.f;
#pragma unroll 8
            for (int c = 0; c < C; c++)
                acc += cs3[(c*3 + k)*3 + v] * kwh[c*32 + c2];
            W[(v*3 + k)*32 + c2] = acc;
        }
        __syncthreads();
        float* dst = tab ? g_Gy : g_Gx;
        for (int q = t; q < 288; q += 256) {
            int v = q / 96, p = q % 96;
            float val = 0.f;
#pragma unroll
            for (int k = 0; k < 3; k++) {
                int ppos = p + k - 1;
                if (ppos < 0 || ppos >= I) continue;
#pragma unroll 8
                for (int c2 = 0; c2 < C2; c2++)
                    val += W[(v*3 + k)*32 + c2] * pxs[c2*96 + ppos];
            }
            dst[((h*C + o)*3 + v)*I + p] = val * SCALE;
        }
    }
}

// ============================================================================
// Launch 2 — tiny: Cs[n,h,o,v] and Av[n,h,d] from KS2/KB2/M/vw.
// grid 64 (n*H + h), 96 threads
// ============================================================================
__global__ void __launch_bounds__(96) k_csav(const float* __restrict__ vw,
                                             const float* __restrict__ vb) {
    __shared__ float sM[C2];
    int b = blockIdx.x;               // n*H + h
    int h = b & 7;
    int t = threadIdx.x;
    if (t < C2) sM[t] = g_M[b*C2 + t];
    __syncthreads();
    if (t < C) {
        // Av
        const float* vwr = vw + (h*C + t)*C;
        float av = vb[h*C + t];
#pragma unroll 8
        for (int c2 = 0; c2 < C2; c2++)
            av += (vwr[c2] + vwr[c2 + C2]) * sM[c2];
        g_Av[b*C + t] = av;
        // Cs (9 variants)
        const float* ks = g_KS2 + (h*C + t)*9*C2;
        const float* kb2 = g_KB2 + (h*C + t)*9;
#pragma unroll
        for (int v = 0; v < 9; v++) {
            float acc = kb2[v];
#pragma unroll 8
            for (int c2 = 0; c2 < C2; c2++)
                acc += sM[c2] * ks[v*C2 + c2];
            g_Cs[(b*C + t)*9 + v] = acc;
        }
    }
}

// ============================================================================
// Launch 3 — k_WTP (exact R4 structure): all 321 MB of stores.
// grid (24, 64, 8), 96 threads
// ============================================================================
__global__ void __launch_bounds__(96) k_WTP(const float* __restrict__ px,
                                            const float* __restrict__ py,
                                            float* __restrict__ out) {
    __shared__ float sGx[H][I];    // vy = 1 slice
    __shared__ float sVx[H][I];
    __shared__ float sPx[I];
    __shared__ float sBase[32], sE0[32], sE2[32], sVb[32], sPb[32];

    int t = threadIdx.x;
    int bx = blockIdx.x, c = blockIdx.y, n = blockIdx.z;

    if (t < 32) {
        int h = t >> 2, il = t & 3;
        int ii = bx*4 + il;
        int vy = (ii == 0) ? 0 : (ii == (I-1) ? 2 : 1);
        const float* cs = g_Cs + ((n*H + h)*C + c)*9 + vy*3;
        const float* gy = g_Gy + (h*C + c)*3*I;
        sBase[t] = cs[1] + gy[I + ii];
        sE0[t]   = cs[0] + gy[ii];
        sE2[t]   = cs[2] + gy[2*I + ii];
        sVb[t]   = g_Av[(n*H + h)*C + c] + g_Vy[(h*C + c)*I + ii];
        sPb[t]   = (c < C2) ? g_M[(n*H + h)*C2 + c]
                            : g_M[(n*H + h)*C2 + (c - C2)] + __ldg(py + (c - C2)*I + ii);
    }
#pragma unroll
    for (int q = t; q < 2*I; q += 96) {     // 192 float4 slots = 8h x 24
        int h = q / 24, j4 = q % 24;
        *(float4*)&sGx[h][j4*4] = *(const float4*)(g_Gx + ((h*C + c)*3 + 1)*I + j4*4);
        *(float4*)&sVx[h][j4*4] = *(const float4*)(g_Vx + (h*C + c)*I + j4*4);
    }
    if (c < C2 && t < 24)
        *(float4*)&sPx[t*4] = *(const float4*)(px + c*I + t*4);
    __syncthreads();

    int j4 = t % 24, il = t / 24;
    int ii = bx*4 + il, jj0 = j4*4;
    int vy = (ii == 0) ? 0 : (ii == (I-1) ? 2 : 1);
    int hb = il;

    float s[H][4];
    float mx0 = -1e30f, mx1 = -1e30f, mx2 = -1e30f, mx3 = -1e30f;
#pragma unroll
    for (int h = 0; h < H; h++) {
        float4 gx = (vy == 1) ? *(const float4*)&sGx[h][jj0]
                              : *(const float4*)(g_Gx + ((h*C + c)*3 + vy)*I + jj0);
        float base = sBase[h*4 + hb];
        float s0 = base + gx.x, s1 = base + gx.y, s2 = base + gx.z, s3 = base + gx.w;
        if (jj0 == 0)     s0 = sE0[h*4 + hb] + gx.x;
        if (jj0 == I - 4) s3 = sE2[h*4 + hb] + gx.w;
        s[h][0] = s0; s[h][1] = s1; s[h][2] = s2; s[h][3] = s3;
        mx0 = fmaxf(mx0, s0); mx1 = fmaxf(mx1, s1);
        mx2 = fmaxf(mx2, s2); mx3 = fmaxf(mx3, s3);
    }
    float sum0 = 0.f, sum1 = 0.f, sum2 = 0.f, sum3 = 0.f;
#pragma unroll
    for (int h = 0; h < H; h++) {
        s[h][0] = __expf(s[h][0] - mx0); sum0 += s[h][0];
        s[h][1] = __expf(s[h][1] - mx1); sum1 += s[h][1];
        s[h][2] = __expf(s[h][2] - mx2); sum2 += s[h][2];
        s[h][3] = __expf(s[h][3] - mx3); sum3 += s[h][3];
    }
    float i0 = __fdividef(1.f, sum0), i1 = __fdividef(1.f, sum1);
    float i2 = __fdividef(1.f, sum2), i3 = __fdividef(1.f, sum3);

    float4 px4 = make_float4(0.f, 0.f, 0.f, 0.f);
    if (c < C2) px4 = *(const float4*)&sPx[jj0];

    float4 acc = make_float4(0.f, 0.f, 0.f, 0.f);
    int pixbase = ii*I + jj0;
#pragma unroll
    for (int h = 0; h < H; h++) {
        float w0 = s[h][0]*i0, w1 = s[h][1]*i1, w2 = s[h][2]*i2, w3 = s[h][3]*i3;
        size_t idx = (size_t)((n*H + h)*C + c)*I*I + pixbase;
        __stcs((float4*)(out + OFF_W + idx), make_float4(w0, w1, w2, w3));

        float vbv = sVb[h*4 + hb];
        const float4 vx4 = *(const float4*)&sVx[h][jj0];
        acc.x += w0*(vbv + vx4.x);
        acc.y += w1*(vbv + vx4.y);
        acc.z += w2*(vbv + vx4.z);
        acc.w += w3*(vbv + vx4.w);

        float pb = sPb[h*4 + hb];
        float4 pv = (c < C2) ? make_float4(pb + px4.x, pb + px4.y, pb + px4.z, pb + px4.w)
                             : make_float4(pb, pb, pb, pb);
        __stcs((float4*)(out + OFF_P + idx), pv);
    }
    __stcs((float4*)(out + OFF_T + (size_t)(n*C + c)*I*I + pixbase), acc);
}

// ---------------- launch ----------------
extern "C" void kernel_launch(void* const* d_in, const int* in_sizes, int n_in,
                              void* d_out, int out_size) {
    (void)in_sizes; (void)n_in; (void)out_size;
    const float* X     = (const float*)d_in[0];
    const float* lin_w = (const float*)d_in[1];
    const float* lin_b = (const float*)d_in[2];
    const float* gamma = (const float*)d_in[3];
    const float* beta  = (const float*)d_in[4];
    const float* px    = (const float*)d_in[5];
    const float* py    = (const float*)d_in[6];
    const float* kw    = (const float*)d_in[7];
    const float* kb    = (const float*)d_in[8];
    const float* vw    = (const float*)d_in[9];
    const float* vb    = (const float*)d_in[10];
    const float* sw    = (const float*)d_in[11];
    const float* sb    = (const float*)d_in[12];
    float* out = (float*)d_out;

    k_setup<<<2304, 256>>>(X, lin_w, lin_b, gamma, beta, px, py, kw, kb, vw, sw, sb, out);
    k_csav<<<NN*H, 96>>>(vw, vb);
    k_WTP<<<dim3(I/4, C, NN), 96>>>(px, py, out);
}